// round 14
// baseline (speedup 1.0000x reference)
#include <cuda_runtime.h>
#include <cuda_bf16.h>
#include <cstdint>

// DistortionLoss via warp-private cp.async staging + hierarchical pairwise merge.
//   ordered split A|B: pair(A∪B) = pair(A) + pair(B) + TW_A*TWS_B - TWS_A*TW_B
//   TW = sum w, TWS = sum w*s, s_k = z_k + z_{k+1} (raw z-space; near cancels,
//   inv = 1/(far-near) applied once).
//
// R14 = R12 (best measured: ncu 5.79us) with tail trims:
//  - final butterfly level computes only T (W/WS accumulation dropped — their
//    values are dead after the last cross term).
// Structure: 2 rays per warp (half-warp each), 8 elems/thread streamed in
// registers; warp-private smem staging via cp.async (coalesced, non-overlapping
// quads); no block barriers — commit/wait + __syncwarp only.

#define FULL 0xFFFFFFFFu

__device__ __forceinline__ void cp_async16(void* smem_dst, const void* gmem_src) {
    uint32_t s = (uint32_t)__cvta_generic_to_shared(smem_dst);
    asm volatile("cp.async.cg.shared.global [%0], [%1], 16;\n" :: "r"(s), "l"(gmem_src));
}

__global__ void __launch_bounds__(256) distortion_loss_kernel(
    const float*  __restrict__ w,     // [R,128]
    const float*  __restrict__ z,     // [R,129]
    const float*  __restrict__ nearp, // [R]
    const float*  __restrict__ farp,  // [R]
    float* __restrict__ out)          // [R]
{
    __shared__ float sm[8][520];      // per-warp slab: w[0..256) + z[256..516)

    const int lane = threadIdx.x & 31;
    const int wc   = threadIdx.x >> 5;            // warp within CTA
    const int gw   = blockIdx.x * 8 + wc;         // global warp id -> rays 2gw, 2gw+1
    const int h    = lane >> 4;                   // ray within warp (half)
    const int t    = lane & 15;                   // thread within ray

    float* wbuf = sm[wc];
    float* zbuf = sm[wc] + 256;

    // ---- warp-private staging (all quads 16B-aligned, coalesced) ----
    {
        const float4* wsrc = reinterpret_cast<const float4*>(w) + (size_t)gw * 64;
        cp_async16(wbuf + 4 * lane,        wsrc + lane);
        cp_async16(wbuf + 4 * (lane + 32), wsrc + lane + 32);
    }
    const int zf = 258 * gw;                      // first z float of the ray pair
    const int qa = zf >> 2;                       // covering aligned quad
    const int r  = zf & 3;                        // 0 or 2 (uniform per warp)
    {
        const float4* zsrc = reinterpret_cast<const float4*>(z) + qa;
        cp_async16(zbuf + 4 * lane,        zsrc + lane);
        cp_async16(zbuf + 4 * (lane + 32), zsrc + lane + 32);
        if (lane == 0) cp_async16(zbuf + 4 * 64, zsrc + 64);   // 65th quad
    }
    asm volatile("cp.async.commit_group;\n" ::: "memory");

    // overlap: near/far + reciprocal while the copies fly
    const int ray  = 2 * gw + h;
    const float nr = __ldg(nearp + ray);
    const float fr = __ldg(farp  + ray);
    const float inv = __fdividef(1.0f, fr - nr);

    asm volatile("cp.async.wait_group 0;\n" ::: "memory");
    __syncwarp();

    // ---- w: 8 floats (2 aligned quads) at h*128 + 8t ----
    const float4* wv4 = reinterpret_cast<const float4*>(wbuf + h * 128 + 8 * t);
    const float4 wa = wv4[0], wb = wv4[1];

    // ---- z: 12 staged floats covering elements 8t..8t+8 of this ray ----
    const int f0  = r + h * 129 + 8 * t;          // float index in zbuf
    const float4* zb4 = reinterpret_cast<const float4*>(zbuf) + (f0 >> 2);
    const float4 za = zb4[0], zb = zb4[1], zc = zb4[2];
    const int off = f0 & 3;                       // = (r+h)&3, uniform per half

    float zl[9];
    if (off == 0) {
        zl[0]=za.x; zl[1]=za.y; zl[2]=za.z; zl[3]=za.w;
        zl[4]=zb.x; zl[5]=zb.y; zl[6]=zb.z; zl[7]=zb.w; zl[8]=zc.x;
    } else if (off == 1) {
        zl[0]=za.y; zl[1]=za.z; zl[2]=za.w;
        zl[3]=zb.x; zl[4]=zb.y; zl[5]=zb.z; zl[6]=zb.w; zl[7]=zc.x; zl[8]=zc.y;
    } else if (off == 2) {
        zl[0]=za.z; zl[1]=za.w;
        zl[2]=zb.x; zl[3]=zb.y; zl[4]=zb.z; zl[5]=zb.w; zl[6]=zc.x; zl[7]=zc.y; zl[8]=zc.z;
    } else {
        zl[0]=za.w;
        zl[1]=zb.x; zl[2]=zb.y; zl[3]=zb.z; zl[4]=zb.w;
        zl[5]=zc.x; zl[6]=zc.y; zl[7]=zc.z; zl[8]=zc.w;
    }

    const float wl[8] = {wa.x, wa.y, wa.z, wa.w, wb.x, wb.y, wb.z, wb.w};

    // ---- 8-element serial stream: T (pairwise), W, WS, qq (w^2 dz) ----
    float T = 0.f, W = 0.f, WS = 0.f, qq = 0.f;
    #pragma unroll
    for (int k = 0; k < 8; k++) {
        const float wk = wl[k];
        const float s  = zl[k] + zl[k + 1];
        T  = fmaf(wk, fmaf(s, W, -WS), T);        // w_k*(s_k*W_< - WS_<)
        qq = fmaf(wk * wk, zl[k + 1] - zl[k], qq);
        W += wk;
        WS = fmaf(wk, s, WS);
    }
    T = fmaf(qq, (1.0f / 3.0f), T);               // fold linear term (merge-safe)

    // ---- xor-butterfly merge of (T, W, WS) within the 16-lane half ----
    // levels 1,2,4: full (T,W,WS) update; level 8: T only (W/WS dead after)
    #pragma unroll
    for (int o = 1; o < 8; o <<= 1) {
        const float pT  = __shfl_xor_sync(FULL, T,  o);
        const float pW  = __shfl_xor_sync(FULL, W,  o);
        const float pWS = __shfl_xor_sync(FULL, WS, o);
        const float c   = fmaf(W, pWS, -(WS * pW));
        const float sgn = (t & o) ? -1.0f : 1.0f;
        T = fmaf(sgn, c, T + pT);
        W  += pW;
        WS += pWS;
    }
    {
        const float pT  = __shfl_xor_sync(FULL, T,  8);
        const float pW  = __shfl_xor_sync(FULL, W,  8);
        const float pWS = __shfl_xor_sync(FULL, WS, 8);
        const float c   = fmaf(W, pWS, -(WS * pW));
        const float sgn = (t & 8) ? -1.0f : 1.0f;
        T = fmaf(sgn, c, T + pT);
    }

    if (t == 0)
        out[ray] = T * inv;
}

extern "C" void kernel_launch(void* const* d_in, const int* in_sizes, int n_in,
                              void* d_out, int out_size)
{
    const float* w   = (const float*)d_in[0]; // weights [R,128,1]
    const float* z   = (const float*)d_in[1]; // z_vals  [R,129]
    const float* nr  = (const float*)d_in[2]; // near    [R,1]
    const float* fr  = (const float*)d_in[3]; // far     [R,1]
    float*       out = (float*)d_out;         // [R,1]

    const int R = in_sizes[0] / 128;          // 8192
    // 2 rays per warp, 8 warps per CTA -> 16 rays per CTA
    distortion_loss_kernel<<<R / 16, 256>>>(w, z, nr, fr, out);
}

// round 15
// speedup vs baseline: 1.0049x; 1.0049x over previous
#include <cuda_runtime.h>
#include <cuda_bf16.h>
#include <cstdint>

// DistortionLoss via warp-private cp.async staging + hierarchical pairwise merge.
//
//   ordered split A|B: pair(A∪B) = pair(A) + pair(B) + TW_A*TWS_B - TWS_A*TW_B
//   TW = sum w, TWS = sum w*s, s_k = z_k + z_{k+1} (raw z-space; near cancels,
//   inv = 1/(far-near) applied once at the end).
//
// Final form (R15): R12 structure (best measured ncu, 5.79us) + R14 tail trim
// (last butterfly level computes T only) + branch-free staging of the 65th
// z-quad. 2 rays per warp (half-warp each), 8 elems/thread streamed in
// registers; warp-private smem staging via cp.async (coalesced, non-
// overlapping quads); no block barriers — commit/wait + __syncwarp only.
//
// 14 rounds of evidence: this problem is launch-ramp + DRAM-latency floor
// bound (~10K cycles); all pipes <18%, four distinct structures within 2%.

#define FULL 0xFFFFFFFFu

__device__ __forceinline__ void cp_async16(void* smem_dst, const void* gmem_src) {
    uint32_t s = (uint32_t)__cvta_generic_to_shared(smem_dst);
    asm volatile("cp.async.cg.shared.global [%0], [%1], 16;\n" :: "r"(s), "l"(gmem_src));
}

__global__ void __launch_bounds__(256) distortion_loss_kernel(
    const float*  __restrict__ w,     // [R,128]
    const float*  __restrict__ z,     // [R,129]
    const float*  __restrict__ nearp, // [R]
    const float*  __restrict__ farp,  // [R]
    float* __restrict__ out)          // [R]
{
    __shared__ float sm[8][520];      // per-warp slab: w[0..256) + z[256..516)

    const int lane = threadIdx.x & 31;
    const int wc   = threadIdx.x >> 5;            // warp within CTA
    const int gw   = blockIdx.x * 8 + wc;         // global warp id -> rays 2gw, 2gw+1
    const int h    = lane >> 4;                   // ray within warp (half)
    const int t    = lane & 15;                   // thread within ray

    float* wbuf = sm[wc];
    float* zbuf = sm[wc] + 256;

    // ---- warp-private staging (all quads 16B-aligned, coalesced) ----
    {
        const float4* wsrc = reinterpret_cast<const float4*>(w) + (size_t)gw * 64;
        cp_async16(wbuf + 4 * lane,        wsrc + lane);
        cp_async16(wbuf + 4 * (lane + 32), wsrc + lane + 32);
    }
    const int zf = 258 * gw;                      // first z float of the ray pair
    const int qa = zf >> 2;                       // covering aligned quad
    const int r  = zf & 3;                        // 0 or 2 (uniform per warp)
    {
        const float4* zsrc = reinterpret_cast<const float4*>(z) + qa;
        cp_async16(zbuf + 4 * lane, zsrc + lane);
        // quads 32..64: 33 quads for 32 lanes; lane 0 covers both 32 and 64
        // branch-free: lane l copies quad 32+l, lane 0 additionally quad 64
        cp_async16(zbuf + 4 * (lane + 32), zsrc + lane + 32);
        const int extra = (lane == 0) ? 64 : (lane + 32);   // lane0 re-targets; others repeat (idempotent)
        cp_async16(zbuf + 4 * extra, zsrc + extra);
    }
    asm volatile("cp.async.commit_group;\n" ::: "memory");

    // overlap: near/far + reciprocal while the copies fly
    const int ray  = 2 * gw + h;
    const float nr = __ldg(nearp + ray);
    const float fr = __ldg(farp  + ray);
    const float inv = __fdividef(1.0f, fr - nr);

    asm volatile("cp.async.wait_group 0;\n" ::: "memory");
    __syncwarp();

    // ---- w: 8 floats (2 aligned quads) at h*128 + 8t ----
    const float4* wv4 = reinterpret_cast<const float4*>(wbuf + h * 128 + 8 * t);
    const float4 wa = wv4[0], wb = wv4[1];

    // ---- z: 12 staged floats covering elements 8t..8t+8 of this ray ----
    const int f0  = r + h * 129 + 8 * t;          // float index in zbuf
    const float4* zb4 = reinterpret_cast<const float4*>(zbuf) + (f0 >> 2);
    const float4 za = zb4[0], zb = zb4[1], zc = zb4[2];
    const int off = f0 & 3;                       // = (r+h)&3, uniform per half

    float zl[9];
    if (off == 0) {
        zl[0]=za.x; zl[1]=za.y; zl[2]=za.z; zl[3]=za.w;
        zl[4]=zb.x; zl[5]=zb.y; zl[6]=zb.z; zl[7]=zb.w; zl[8]=zc.x;
    } else if (off == 1) {
        zl[0]=za.y; zl[1]=za.z; zl[2]=za.w;
        zl[3]=zb.x; zl[4]=zb.y; zl[5]=zb.z; zl[6]=zb.w; zl[7]=zc.x; zl[8]=zc.y;
    } else if (off == 2) {
        zl[0]=za.z; zl[1]=za.w;
        zl[2]=zb.x; zl[3]=zb.y; zl[4]=zb.z; zl[5]=zb.w; zl[6]=zc.x; zl[7]=zc.y; zl[8]=zc.z;
    } else {
        zl[0]=za.w;
        zl[1]=zb.x; zl[2]=zb.y; zl[3]=zb.z; zl[4]=zb.w;
        zl[5]=zc.x; zl[6]=zc.y; zl[7]=zc.z; zl[8]=zc.w;
    }

    const float wl[8] = {wa.x, wa.y, wa.z, wa.w, wb.x, wb.y, wb.z, wb.w};

    // ---- 8-element serial stream: T (pairwise), W, WS, qq (w^2 dz) ----
    float T = 0.f, W = 0.f, WS = 0.f, qq = 0.f;
    #pragma unroll
    for (int k = 0; k < 8; k++) {
        const float wk = wl[k];
        const float s  = zl[k] + zl[k + 1];
        T  = fmaf(wk, fmaf(s, W, -WS), T);        // w_k*(s_k*W_< - WS_<)
        qq = fmaf(wk * wk, zl[k + 1] - zl[k], qq);
        W += wk;
        WS = fmaf(wk, s, WS);
    }
    T = fmaf(qq, (1.0f / 3.0f), T);               // fold linear term (merge-safe)

    // ---- xor-butterfly merge of (T, W, WS) within the 16-lane half ----
    // levels 1,2,4: full (T,W,WS) update; level 8: T only (W/WS dead after)
    #pragma unroll
    for (int o = 1; o < 8; o <<= 1) {
        const float pT  = __shfl_xor_sync(FULL, T,  o);
        const float pW  = __shfl_xor_sync(FULL, W,  o);
        const float pWS = __shfl_xor_sync(FULL, WS, o);
        const float c   = fmaf(W, pWS, -(WS * pW));
        const float sgn = (t & o) ? -1.0f : 1.0f;
        T = fmaf(sgn, c, T + pT);
        W  += pW;
        WS += pWS;
    }
    {
        const float pT  = __shfl_xor_sync(FULL, T,  8);
        const float pW  = __shfl_xor_sync(FULL, W,  8);
        const float pWS = __shfl_xor_sync(FULL, WS, 8);
        const float c   = fmaf(W, pWS, -(WS * pW));
        const float sgn = (t & 8) ? -1.0f : 1.0f;
        T = fmaf(sgn, c, T + pT);
    }

    if (t == 0)
        out[ray] = T * inv;
}

extern "C" void kernel_launch(void* const* d_in, const int* in_sizes, int n_in,
                              void* d_out, int out_size)
{
    const float* w   = (const float*)d_in[0]; // weights [R,128,1]
    const float* z   = (const float*)d_in[1]; // z_vals  [R,129]
    const float* nr  = (const float*)d_in[2]; // near    [R,1]
    const float* fr  = (const float*)d_in[3]; // far     [R,1]
    float*       out = (float*)d_out;         // [R,1]

    const int R = in_sizes[0] / 128;          // 8192
    // 2 rays per warp, 8 warps per CTA -> 16 rays per CTA
    distortion_loss_kernel<<<R / 16, 256>>>(w, z, nr, fr, out);
}